// round 6
// baseline (speedup 1.0000x reference)
#include <cuda_runtime.h>
#include <cuda_bf16.h>
#include <cstdint>

// Loss_58042188038797:
//   ri = i / (n*(n+1)/2)
//   p_win = victor==0 ? f[:,0] : f[:,1]
//   loss = -sum( (log(p_win) - (f[:,0]-0.5)^2) * ri )
//
// R3 structure (separate zero kernel + atomicAdd finish — measured free
// under graph replay; fused last-block-done cost +0.8us) with R3's exact
// loop body (best DRAM%: 80.9). Change: BLOCK 256->512, GRID 1184->592.
// Same thread count; oe drops 8->4 CTAs/SM, halving the cross-CTA
// L1tex-queue contention product (oe*MLP_p1: 24 -> 12).

static constexpr int BLOCK = 512;
static constexpr int GRID  = 148 * 4;

__global__ void zero_out_kernel(float* out) {
    if (blockIdx.x == 0 && threadIdx.x == 0) out[0] = 0.0f;
}

__global__ __launch_bounds__(BLOCK) void loss_kernel(
    const float4* __restrict__ fo,   // final_out as float4 (2 elems/vec)
    const int4*  __restrict__ pv,    // point_victor as int4 (4 elems/vec)
    float* __restrict__ out,
    int n4,                          // n / 4
    float inv_denom)                 // 2 / (n*(n+1))
{
    float acc = 0.0f;
    const int stride = gridDim.x * blockDim.x;

    for (int i = blockIdx.x * blockDim.x + threadIdx.x; i < n4; i += stride) {
        float4 a = fo[2 * i];        // elems 4i, 4i+1
        float4 b = fo[2 * i + 1];    // elems 4i+2, 4i+3
        int4   v = pv[i];
        float base = (float)(4 * i); // 4i < 2^24 -> exact in f32

        {
            float p = (v.x == 0) ? a.x : a.y;
            float d = a.x - 0.5f;
            float t = __logf(p) - d * d;
            acc = fmaf(t, (base + 0.0f) * inv_denom, acc);
        }
        {
            float p = (v.y == 0) ? a.z : a.w;
            float d = a.z - 0.5f;
            float t = __logf(p) - d * d;
            acc = fmaf(t, (base + 1.0f) * inv_denom, acc);
        }
        {
            float p = (v.z == 0) ? b.x : b.y;
            float d = b.x - 0.5f;
            float t = __logf(p) - d * d;
            acc = fmaf(t, (base + 2.0f) * inv_denom, acc);
        }
        {
            float p = (v.w == 0) ? b.z : b.w;
            float d = b.z - 0.5f;
            float t = __logf(p) - d * d;
            acc = fmaf(t, (base + 3.0f) * inv_denom, acc);
        }
    }

    // warp reduce
    #pragma unroll
    for (int o = 16; o > 0; o >>= 1)
        acc += __shfl_down_sync(0xFFFFFFFFu, acc, o);

    __shared__ float smem[BLOCK / 32];
    const int lane = threadIdx.x & 31;
    const int wid  = threadIdx.x >> 5;
    if (lane == 0) smem[wid] = acc;
    __syncthreads();

    if (wid == 0) {
        acc = (lane < BLOCK / 32) ? smem[lane] : 0.0f;
        #pragma unroll
        for (int o = 8; o > 0; o >>= 1)
            acc += __shfl_down_sync(0xFFFFFFFFu, acc, o);
        if (lane == 0)
            atomicAdd(out, -acc);   // loss = -sum
    }
}

extern "C" void kernel_launch(void* const* d_in, const int* in_sizes, int n_in,
                              void* d_out, int out_size) {
    const float4* fo = (const float4*)d_in[0];   // final_out (N,2) f32
    const int4*   pv = (const int4*)d_in[1];     // point_victor (N) i32
    float* out = (float*)d_out;

    const int n  = in_sizes[1];                  // N
    const int n4 = n / 4;                        // N = 2^24, divisible by 4

    const double nd = (double)n;
    const float inv_denom = (float)(2.0 / (nd * (nd + 1.0)));

    zero_out_kernel<<<1, 32>>>(out);
    loss_kernel<<<GRID, BLOCK>>>(fo, pv, out, n4, inv_denom);
}

// round 7
// speedup vs baseline: 1.0119x; 1.0119x over previous
#include <cuda_runtime.h>
#include <cuda_bf16.h>
#include <cstdint>

// Loss_58042188038797:
//   ri = i / (n*(n+1)/2)
//   p_win = victor==0 ? f[:,0] : f[:,1]
//   loss = -sum( (log(p_win) - (f[:,0]-0.5)^2) * ri )
//
// FINAL (R3 revert — empirical best across R3-R6 sweep):
//   - plain cached float4/int4 grid-stride loads (MLP_p1=3):
//     80.9% DRAM / 6414 GB/s, best of all variants tried
//   - BLOCK=256, GRID=148*8 (one full-occupancy wave)
//   - separate 1-thread zeroing launch (free under graph replay;
//     fused last-block-done variant measured +0.8us)
//   - sweep results: __ldcs+2x unroll -> 76.1% DRAM; fusion -> 89.5% occ,
//     +0.8us tail; block=512 -> 78.2% DRAM. All regressions.
// Remaining gap to 8 TB/s spec is the LTS/HBM ceiling for this
// read-once 12 B/elem mixed stream; traffic is irreducible.

static constexpr int BLOCK = 256;
static constexpr int GRID  = 148 * 8;

__global__ void zero_out_kernel(float* out) {
    if (blockIdx.x == 0 && threadIdx.x == 0) out[0] = 0.0f;
}

__global__ __launch_bounds__(BLOCK) void loss_kernel(
    const float4* __restrict__ fo,   // final_out as float4: 2 elems per vec
    const int4*  __restrict__ pv,    // point_victor as int4: 4 elems per vec
    float* __restrict__ out,
    int n4,                          // n / 4
    float inv_denom)                 // 2 / (n*(n+1))
{
    float acc = 0.0f;
    const int stride = gridDim.x * blockDim.x;

    for (int i = blockIdx.x * blockDim.x + threadIdx.x; i < n4; i += stride) {
        float4 a = fo[2 * i];        // elems 4i, 4i+1
        float4 b = fo[2 * i + 1];    // elems 4i+2, 4i+3
        int4   v = pv[i];
        float base = (float)(4 * i); // 4i < 2^24 -> exact in f32

        // elem 0: f0=a.x f1=a.y
        {
            float p = (v.x == 0) ? a.x : a.y;
            float d = a.x - 0.5f;
            float t = __logf(p) - d * d;
            acc = fmaf(t, (base + 0.0f) * inv_denom, acc);
        }
        // elem 1: f0=a.z f1=a.w
        {
            float p = (v.y == 0) ? a.z : a.w;
            float d = a.z - 0.5f;
            float t = __logf(p) - d * d;
            acc = fmaf(t, (base + 1.0f) * inv_denom, acc);
        }
        // elem 2: f0=b.x f1=b.y
        {
            float p = (v.z == 0) ? b.x : b.y;
            float d = b.x - 0.5f;
            float t = __logf(p) - d * d;
            acc = fmaf(t, (base + 2.0f) * inv_denom, acc);
        }
        // elem 3: f0=b.z f1=b.w
        {
            float p = (v.w == 0) ? b.z : b.w;
            float d = b.z - 0.5f;
            float t = __logf(p) - d * d;
            acc = fmaf(t, (base + 3.0f) * inv_denom, acc);
        }
    }

    // warp reduce
    #pragma unroll
    for (int o = 16; o > 0; o >>= 1)
        acc += __shfl_down_sync(0xFFFFFFFFu, acc, o);

    __shared__ float smem[BLOCK / 32];
    const int lane = threadIdx.x & 31;
    const int wid  = threadIdx.x >> 5;
    if (lane == 0) smem[wid] = acc;
    __syncthreads();

    if (wid == 0) {
        acc = (lane < BLOCK / 32) ? smem[lane] : 0.0f;
        #pragma unroll
        for (int o = 4; o > 0; o >>= 1)
            acc += __shfl_down_sync(0xFFFFFFFFu, acc, o);
        if (lane == 0)
            atomicAdd(out, -acc);   // loss = -sum
    }
}

extern "C" void kernel_launch(void* const* d_in, const int* in_sizes, int n_in,
                              void* d_out, int out_size) {
    const float4* fo = (const float4*)d_in[0];   // final_out (N,2) f32
    const int4*   pv = (const int4*)d_in[1];     // point_victor (N) i32
    float* out = (float*)d_out;

    const int n = in_sizes[1];                   // N (element count of victor)
    const int n4 = n / 4;                        // N = 2^24, divisible by 4

    // inv_denom = 2 / (n*(n+1)) computed in double on host for accuracy
    const double nd = (double)n;
    const float inv_denom = (float)(2.0 / (nd * (nd + 1.0)));

    zero_out_kernel<<<1, 32>>>(out);
    loss_kernel<<<GRID, BLOCK>>>(fo, pv, out, n4, inv_denom);
}